// round 3
// baseline (speedup 1.0000x reference)
#include <cuda_runtime.h>
#include <cuda_bf16.h>
#include <math.h>

#define B_ 4
#define T_ 2048
#define C_ 1024
#define NH_ 16
#define HD_ 64
#define M_ (B_*T_)   // 8192

// Scratch (no allocations allowed): q in [B,NH,T,HD], attention output in [B,T,C]
__device__ float g_q[(size_t)B_*NH_*T_*HD_];
__device__ float g_o[(size_t)B_*T_*C_];

// ---------------------------------------------------------------------------
// QKV GEMM: X[M,C] @ W[C,3C] + b, scatter epilogue:
//   q -> g_q [B,NH,T,HD];  k,v -> d_out k/v regions [B,NH,T,HD]
// Tiles: BM=BN=128, BK=16, 256 threads, 8x8 per-thread microtile.
// ---------------------------------------------------------------------------
__global__ __launch_bounds__(256) void qkv_gemm(const float* __restrict__ X,
                                                const float* __restrict__ W,
                                                const float* __restrict__ bias,
                                                float* __restrict__ outK,
                                                float* __restrict__ outV) {
    const int K = C_, N = 3 * C_;
    __shared__ float As[16][128];
    __shared__ float Bs[16][128];
    int tid = threadIdx.x;
    int tx = tid & 15, ty = tid >> 4;
    int m0 = blockIdx.y * 128, n0 = blockIdx.x * 128;
    float acc[8][8] = {};
    for (int k0 = 0; k0 < K; k0 += 16) {
        float4 a[2], b[2];
#pragma unroll
        for (int i = 0; i < 2; ++i) {
            int idx = tid + i * 256;
            int ar = idx >> 2, ac = (idx & 3) * 4;
            a[i] = *(const float4*)(X + (size_t)(m0 + ar) * K + k0 + ac);
            int br = idx >> 5, bc = (idx & 31) * 4;
            b[i] = *(const float4*)(W + (size_t)(k0 + br) * N + n0 + bc);
        }
        __syncthreads();
#pragma unroll
        for (int i = 0; i < 2; ++i) {
            int idx = tid + i * 256;
            int ar = idx >> 2, ac = (idx & 3) * 4;
            As[ac + 0][ar] = a[i].x; As[ac + 1][ar] = a[i].y;
            As[ac + 2][ar] = a[i].z; As[ac + 3][ar] = a[i].w;
            int br = idx >> 5, bc = (idx & 31) * 4;
            *(float4*)&Bs[br][bc] = b[i];
        }
        __syncthreads();
#pragma unroll
        for (int kk = 0; kk < 16; ++kk) {
            float ra[8], rb[8];
            *(float4*)&ra[0] = *(const float4*)&As[kk][ty * 8];
            *(float4*)&ra[4] = *(const float4*)&As[kk][ty * 8 + 4];
            *(float4*)&rb[0] = *(const float4*)&Bs[kk][tx * 8];
            *(float4*)&rb[4] = *(const float4*)&Bs[kk][tx * 8 + 4];
#pragma unroll
            for (int i = 0; i < 8; ++i)
#pragma unroll
                for (int j = 0; j < 8; ++j)
                    acc[i][j] += ra[i] * rb[j];
        }
    }
    // Scatter epilogue
#pragma unroll
    for (int i = 0; i < 8; ++i) {
        int m = m0 + ty * 8 + i;
        int bb = m >> 11, t = m & (T_ - 1);
#pragma unroll
        for (int j = 0; j < 8; ++j) {
            int n = n0 + tx * 8 + j;
            float v = acc[i][j] + bias[n];
            int region = n >> 10;          // 0=q, 1=k, 2=v
            int c = n & (C_ - 1);
            int h = c >> 6, d = c & 63;
            size_t dst = ((size_t)(bb * NH_ + h) * T_ + t) * HD_ + d;
            if (region == 0)      g_q[dst] = v;
            else if (region == 1) outK[dst] = v;
            else                  outV[dst] = v;
        }
    }
}

// ---------------------------------------------------------------------------
// Output projection GEMM: g_o[M,C] @ W_out[C,C] + b_out -> y [M,C]
// ---------------------------------------------------------------------------
__global__ __launch_bounds__(256) void out_gemm(const float* __restrict__ W,
                                                const float* __restrict__ bias,
                                                float* __restrict__ Y) {
    const int K = C_, N = C_;
    __shared__ float As[16][128];
    __shared__ float Bs[16][128];
    int tid = threadIdx.x;
    int tx = tid & 15, ty = tid >> 4;
    int m0 = blockIdx.y * 128, n0 = blockIdx.x * 128;
    float acc[8][8] = {};
    for (int k0 = 0; k0 < K; k0 += 16) {
        float4 a[2], b[2];
#pragma unroll
        for (int i = 0; i < 2; ++i) {
            int idx = tid + i * 256;
            int ar = idx >> 2, ac = (idx & 3) * 4;
            a[i] = *(const float4*)(g_o + (size_t)(m0 + ar) * K + k0 + ac);
            int br = idx >> 5, bc = (idx & 31) * 4;
            b[i] = *(const float4*)(W + (size_t)(k0 + br) * N + n0 + bc);
        }
        __syncthreads();
#pragma unroll
        for (int i = 0; i < 2; ++i) {
            int idx = tid + i * 256;
            int ar = idx >> 2, ac = (idx & 3) * 4;
            As[ac + 0][ar] = a[i].x; As[ac + 1][ar] = a[i].y;
            As[ac + 2][ar] = a[i].z; As[ac + 3][ar] = a[i].w;
            int br = idx >> 5, bc = (idx & 31) * 4;
            *(float4*)&Bs[br][bc] = b[i];
        }
        __syncthreads();
#pragma unroll
        for (int kk = 0; kk < 16; ++kk) {
            float ra[8], rb[8];
            *(float4*)&ra[0] = *(const float4*)&As[kk][ty * 8];
            *(float4*)&ra[4] = *(const float4*)&As[kk][ty * 8 + 4];
            *(float4*)&rb[0] = *(const float4*)&Bs[kk][tx * 8];
            *(float4*)&rb[4] = *(const float4*)&Bs[kk][tx * 8 + 4];
#pragma unroll
            for (int i = 0; i < 8; ++i)
#pragma unroll
                for (int j = 0; j < 8; ++j)
                    acc[i][j] += ra[i] * rb[j];
        }
    }
#pragma unroll
    for (int i = 0; i < 8; ++i) {
        int m = m0 + ty * 8 + i;
#pragma unroll
        for (int j = 0; j < 8; j += 4) {
            int n = n0 + tx * 8 + j;
            float4 v;
            v.x = acc[i][j + 0] + bias[n + 0];
            v.y = acc[i][j + 1] + bias[n + 1];
            v.z = acc[i][j + 2] + bias[n + 2];
            v.w = acc[i][j + 3] + bias[n + 3];
            *(float4*)(Y + (size_t)m * N + n) = v;
        }
    }
}

// ---------------------------------------------------------------------------
// Flash attention (fp32, causal). 16 q-rows per block (one warp per row).
// KV tiles of 64 rows in smem (pad 65 to kill bank conflicts).
// Each lane owns columns d=lane, lane+32 of the accumulator and scores
// j=lane, lane+32 of each tile. Online softmax, causal tile skipping.
// Reads k,v from their final output slots; writes g_o in [B,T,C].
// ---------------------------------------------------------------------------
#define AT_WARPS 16
__global__ __launch_bounds__(512) void attn_kernel(const float* __restrict__ gk,
                                                   const float* __restrict__ gv) {
    __shared__ float Ks[64 * 65];
    __shared__ float Vs[64 * 65];
    __shared__ float Qs[AT_WARPS][65];
    __shared__ float Ps[AT_WARPS][64];

    int bh = blockIdx.y;                 // b*NH + h
    int q0 = blockIdx.x * AT_WARPS;
    int warp = threadIdx.x >> 5, lane = threadIdx.x & 31;

    const float* qbase = g_q + (size_t)bh * T_ * HD_;
    const float* kbase = gk + (size_t)bh * T_ * HD_;
    const float* vbase = gv + (size_t)bh * T_ * HD_;

    // Load Q rows for this block
    for (int e = threadIdx.x; e < AT_WARPS * 64; e += blockDim.x) {
        int r = e >> 6, d = e & 63;
        Qs[r][d] = qbase[(size_t)(q0 + r) * HD_ + d];
    }

    int qi = q0 + warp;
    float m = -INFINITY, l = 0.f, acc0 = 0.f, acc1 = 0.f;
    int ntiles = (q0 + AT_WARPS - 1) / 64 + 1;   // causal: skip fully-masked tiles

    for (int t = 0; t < ntiles; ++t) {
        int j0 = t * 64;
        __syncthreads();
        for (int e = threadIdx.x; e < 64 * 64; e += blockDim.x) {
            int r = e >> 6, d = e & 63;
            Ks[r * 65 + d] = kbase[(size_t)(j0 + r) * HD_ + d];
            Vs[r * 65 + d] = vbase[(size_t)(j0 + r) * HD_ + d];
        }
        __syncthreads();

        // scores for j = lane and j = lane + 32
        float s0 = 0.f, s1 = 0.f;
        const float* qrow = Qs[warp];
#pragma unroll 8
        for (int d = 0; d < 64; ++d) {
            float qd = qrow[d];
            s0 += qd * Ks[lane * 65 + d];
            s1 += qd * Ks[(lane + 32) * 65 + d];
        }
        s0 *= 0.125f; s1 *= 0.125f;
        if (j0 + lane > qi)      s0 = -INFINITY;
        if (j0 + lane + 32 > qi) s1 = -INFINITY;

        float mt = fmaxf(s0, s1);
#pragma unroll
        for (int off = 16; off > 0; off >>= 1)
            mt = fmaxf(mt, __shfl_xor_sync(0xffffffffu, mt, off));
        float mnew = fmaxf(m, mt);
        float scale = __expf(m - mnew);          // 0 on first tile (m = -inf)
        float p0 = __expf(s0 - mnew);
        float p1 = __expf(s1 - mnew);
        float lt = p0 + p1;
#pragma unroll
        for (int off = 16; off > 0; off >>= 1)
            lt += __shfl_xor_sync(0xffffffffu, lt, off);
        l = l * scale + lt;
        acc0 *= scale; acc1 *= scale;
        m = mnew;

        Ps[warp][lane] = p0;
        Ps[warp][lane + 32] = p1;
        __syncwarp();
#pragma unroll 8
        for (int j = 0; j < 64; ++j) {
            float p = Ps[warp][j];
            acc0 += p * Vs[j * 65 + lane];
            acc1 += p * Vs[j * 65 + lane + 32];
        }
        __syncwarp();
    }

    // write O[b, t, h*64 + d]
    int b = bh >> 4, h = bh & 15;
    float inv = 1.f / l;
    size_t o_off = ((size_t)b * T_ + qi) * C_ + h * HD_;
    g_o[o_off + lane]      = acc0 * inv;
    g_o[o_off + lane + 32] = acc1 * inv;
}

// ---------------------------------------------------------------------------
extern "C" void kernel_launch(void* const* d_in, const int* in_sizes, int n_in,
                              void* d_out, int out_size) {
    const float* x    = (const float*)d_in[0];
    const float* Wqkv = (const float*)d_in[1];
    const float* bqkv = (const float*)d_in[2];
    const float* Wout = (const float*)d_in[3];
    const float* bout = (const float*)d_in[4];

    float* y = (float*)d_out;
    float* k = y + (size_t)B_ * T_ * C_;
    float* v = k + (size_t)B_ * T_ * C_;

    qkv_gemm<<<dim3(3 * C_ / 128, M_ / 128), 256>>>(x, Wqkv, bqkv, k, v);
    attn_kernel<<<dim3(T_ / AT_WARPS, B_ * NH_), 512>>>(k, v);
    out_gemm<<<dim3(C_ / 128, M_ / 128), 256>>>(Wout, bout, y);
}

// round 6
// speedup vs baseline: 1.2944x; 1.2944x over previous
#include <cuda_runtime.h>
#include <cuda_bf16.h>
#include <math.h>
#include <stdint.h>

#define B_ 4
#define T_ 2048
#define C_ 1024
#define NH_ 16
#define HD_ 64
#define M_ (B_*T_)   // 8192

// Scratch (no allocations allowed): q in [B,NH,T,HD], attention output in [B,T,C]
__device__ float g_q[(size_t)B_*NH_*T_*HD_];
__device__ float g_o[(size_t)B_*T_*C_];

// ---------------------------------------------------------------------------
// Tensor-core tf32 GEMM machinery (mma.sync.m16n8k8)
// Block tile 128x128, BK=32, 256 threads (8 warps, each 32x64).
// Double-buffered cp.async. Smem layouts conflict-free for fragment loads:
//   As[stage][128][36]  (bank = 4r+c distinct)
//   Bs[stage][32][136]  (bank = 8c+r distinct)
// ---------------------------------------------------------------------------
#define AS_STRIDE 36
#define BS_STRIDE 136
#define AS_STAGE (128*AS_STRIDE)   // 4608 floats
#define BS_STAGE (32*BS_STRIDE)    // 4352 floats
#define SMEM_FLOATS (2*AS_STAGE + 2*BS_STAGE)
#define SMEM_BYTES (SMEM_FLOATS*4) // 71680

__device__ __forceinline__ uint32_t f2tf32(float f) {
    uint32_t u;
    asm("cvt.rna.tf32.f32 %0, %1;" : "=r"(u) : "f"(f));
    return u;
}

__device__ __forceinline__ void cp16(float* smem_dst, const float* gmem_src) {
    uint32_t s = (uint32_t)__cvta_generic_to_shared(smem_dst);
    asm volatile("cp.async.cg.shared.global [%0], [%1], 16;" :: "r"(s), "l"(gmem_src));
}

__device__ __forceinline__ void mma_tf32(float* cc, const uint32_t* a,
                                         uint32_t b0, uint32_t b1) {
    asm volatile(
        "mma.sync.aligned.m16n8k8.row.col.f32.tf32.tf32.f32 "
        "{%0,%1,%2,%3}, {%4,%5,%6,%7}, {%8,%9}, {%0,%1,%2,%3};"
        : "+f"(cc[0]), "+f"(cc[1]), "+f"(cc[2]), "+f"(cc[3])
        : "r"(a[0]), "r"(a[1]), "r"(a[2]), "r"(a[3]), "r"(b0), "r"(b1));
}

// Mainloop: acc[mt][nt][4] += A[m0:+128, :K] * B[:K, n0:+128] (tf32 mma)
__device__ __forceinline__ void gemm_mainloop(
    const float* __restrict__ A, int lda,
    const float* __restrict__ B, int ldb,
    int K, int m0, int n0, float* sm, float acc[2][8][4])
{
    float* As = sm;
    float* Bs = sm + 2 * AS_STAGE;
    const int tid = threadIdx.x;
    const int lane = tid & 31, warp = tid >> 5;
    const int r = lane >> 2, c = lane & 3;
    const int mb = (warp & 3) * 32, nb = (warp >> 2) * 64;
    const int ITERS = K / 32;

    auto issue_load = [&](int stage, int k0) {
#pragma unroll
        for (int i = 0; i < 4; ++i) {
            int idx = tid + i * 256;
            int ar = idx >> 3, ac = (idx & 7) * 4;
            cp16(&As[stage * AS_STAGE + ar * AS_STRIDE + ac],
                 A + (size_t)(m0 + ar) * lda + k0 + ac);
            int br = idx >> 5, bc = (idx & 31) * 4;
            cp16(&Bs[stage * BS_STAGE + br * BS_STRIDE + bc],
                 B + (size_t)(k0 + br) * ldb + n0 + bc);
        }
        asm volatile("cp.async.commit_group;");
    };

    issue_load(0, 0);

    for (int it = 0; it < ITERS; ++it) {
        if (it + 1 < ITERS) {
            issue_load((it + 1) & 1, (it + 1) * 32);
            asm volatile("cp.async.wait_group 1;");
        } else {
            asm volatile("cp.async.wait_group 0;");
        }
        __syncthreads();

        const float* as = As + (it & 1) * AS_STAGE;
        const float* bs = Bs + (it & 1) * BS_STAGE;
#pragma unroll
        for (int ks = 0; ks < 4; ++ks) {
            int kb = ks * 8;
            uint32_t afrag[2][4];
#pragma unroll
            for (int mt = 0; mt < 2; ++mt) {
                int row = mb + mt * 16;
                afrag[mt][0] = f2tf32(as[(row + r) * AS_STRIDE + kb + c]);
                afrag[mt][1] = f2tf32(as[(row + r + 8) * AS_STRIDE + kb + c]);
                afrag[mt][2] = f2tf32(as[(row + r) * AS_STRIDE + kb + c + 4]);
                afrag[mt][3] = f2tf32(as[(row + r + 8) * AS_STRIDE + kb + c + 4]);
            }
#pragma unroll
            for (int nt = 0; nt < 8; ++nt) {
                int col = nb + nt * 8 + r;
                uint32_t b0 = f2tf32(bs[(kb + c) * BS_STRIDE + col]);
                uint32_t b1 = f2tf32(bs[(kb + c + 4) * BS_STRIDE + col]);
#pragma unroll
                for (int mt = 0; mt < 2; ++mt)
                    mma_tf32(acc[mt][nt], afrag[mt], b0, b1);
            }
        }
        __syncthreads();
    }
}

// ---------------------------------------------------------------------------
// QKV GEMM: X[M,C] @ W[C,3C] + b, scatter epilogue:
//   q -> g_q [B,NH,T,HD];  k,v -> d_out k/v regions [B,NH,T,HD]
// ---------------------------------------------------------------------------
__global__ __launch_bounds__(256) void qkv_gemm(const float* __restrict__ X,
                                                const float* __restrict__ W,
                                                const float* __restrict__ bias,
                                                float* __restrict__ outK,
                                                float* __restrict__ outV) {
    extern __shared__ float sm[];
    int m0 = blockIdx.y * 128, n0 = blockIdx.x * 128;
    float acc[2][8][4];
#pragma unroll
    for (int i = 0; i < 2; ++i)
#pragma unroll
        for (int j = 0; j < 8; ++j)
#pragma unroll
            for (int p = 0; p < 4; ++p) acc[i][j][p] = 0.f;

    gemm_mainloop(X, C_, W, 3 * C_, C_, m0, n0, sm, acc);

    const int lane = threadIdx.x & 31, warp = threadIdx.x >> 5;
    const int r = lane >> 2, c = lane & 3;
    const int mb = (warp & 3) * 32, nb = (warp >> 2) * 64;

#pragma unroll
    for (int mt = 0; mt < 2; ++mt) {
#pragma unroll
        for (int nt = 0; nt < 8; ++nt) {
            int n = n0 + nb + nt * 8 + 2 * c;         // even
            float bx = bias[n], by = bias[n + 1];
            int region = n >> 10;                      // 0=q,1=k,2=v
            int cc = n & (C_ - 1);
            int h = cc >> 6, d = cc & 63;
            float* dstbase = (region == 0) ? g_q : (region == 1) ? outK : outV;
#pragma unroll
            for (int half = 0; half < 2; ++half) {
                int m = m0 + mb + mt * 16 + r + half * 8;
                int bb = m >> 11, t = m & (T_ - 1);
                size_t dst = ((size_t)(bb * NH_ + h) * T_ + t) * HD_ + d;
                float2 v2;
                v2.x = acc[mt][nt][half * 2 + 0] + bx;
                v2.y = acc[mt][nt][half * 2 + 1] + by;
                *(float2*)(dstbase + dst) = v2;
            }
        }
    }
}

// ---------------------------------------------------------------------------
// Output projection GEMM: g_o[M,C] @ W_out[C,C] + b_out -> y [M,C]
// ---------------------------------------------------------------------------
__global__ __launch_bounds__(256) void out_gemm(const float* __restrict__ W,
                                                const float* __restrict__ bias,
                                                float* __restrict__ Y) {
    extern __shared__ float sm[];
    int m0 = blockIdx.y * 128, n0 = blockIdx.x * 128;
    float acc[2][8][4];
#pragma unroll
    for (int i = 0; i < 2; ++i)
#pragma unroll
        for (int j = 0; j < 8; ++j)
#pragma unroll
            for (int p = 0; p < 4; ++p) acc[i][j][p] = 0.f;

    gemm_mainloop(g_o, C_, W, C_, C_, m0, n0, sm, acc);

    const int lane = threadIdx.x & 31, warp = threadIdx.x >> 5;
    const int r = lane >> 2, c = lane & 3;
    const int mb = (warp & 3) * 32, nb = (warp >> 2) * 64;

#pragma unroll
    for (int mt = 0; mt < 2; ++mt) {
#pragma unroll
        for (int nt = 0; nt < 8; ++nt) {
            int n = n0 + nb + nt * 8 + 2 * c;
            float bx = bias[n], by = bias[n + 1];
#pragma unroll
            for (int half = 0; half < 2; ++half) {
                int m = m0 + mb + mt * 16 + r + half * 8;
                float2 v2;
                v2.x = acc[mt][nt][half * 2 + 0] + bx;
                v2.y = acc[mt][nt][half * 2 + 1] + by;
                *(float2*)(Y + (size_t)m * C_ + n) = v2;
            }
        }
    }
}

// ---------------------------------------------------------------------------
// Flash attention (fp32, causal). 16 q-rows per block (one warp per row).
// Unchanged from Round 0 (isolating this round's change to the GEMMs).
// ---------------------------------------------------------------------------
#define AT_WARPS 16
__global__ __launch_bounds__(512) void attn_kernel(const float* __restrict__ gk,
                                                   const float* __restrict__ gv) {
    __shared__ float Ks[64 * 65];
    __shared__ float Vs[64 * 65];
    __shared__ float Qs[AT_WARPS][65];
    __shared__ float Ps[AT_WARPS][64];

    int bh = blockIdx.y;                 // b*NH + h
    int q0 = blockIdx.x * AT_WARPS;
    int warp = threadIdx.x >> 5, lane = threadIdx.x & 31;

    const float* qbase = g_q + (size_t)bh * T_ * HD_;
    const float* kbase = gk + (size_t)bh * T_ * HD_;
    const float* vbase = gv + (size_t)bh * T_ * HD_;

    for (int e = threadIdx.x; e < AT_WARPS * 64; e += blockDim.x) {
        int r = e >> 6, d = e & 63;
        Qs[r][d] = qbase[(size_t)(q0 + r) * HD_ + d];
    }

    int qi = q0 + warp;
    float m = -INFINITY, l = 0.f, acc0 = 0.f, acc1 = 0.f;
    int ntiles = (q0 + AT_WARPS - 1) / 64 + 1;

    for (int t = 0; t < ntiles; ++t) {
        int j0 = t * 64;
        __syncthreads();
        for (int e = threadIdx.x; e < 64 * 64; e += blockDim.x) {
            int r = e >> 6, d = e & 63;
            Ks[r * 65 + d] = kbase[(size_t)(j0 + r) * HD_ + d];
            Vs[r * 65 + d] = vbase[(size_t)(j0 + r) * HD_ + d];
        }
        __syncthreads();

        float s0 = 0.f, s1 = 0.f;
        const float* qrow = Qs[warp];
#pragma unroll 8
        for (int d = 0; d < 64; ++d) {
            float qd = qrow[d];
            s0 += qd * Ks[lane * 65 + d];
            s1 += qd * Ks[(lane + 32) * 65 + d];
        }
        s0 *= 0.125f; s1 *= 0.125f;
        if (j0 + lane > qi)      s0 = -INFINITY;
        if (j0 + lane + 32 > qi) s1 = -INFINITY;

        float mt = fmaxf(s0, s1);
#pragma unroll
        for (int off = 16; off > 0; off >>= 1)
            mt = fmaxf(mt, __shfl_xor_sync(0xffffffffu, mt, off));
        float mnew = fmaxf(m, mt);
        float scale = __expf(m - mnew);
        float p0 = __expf(s0 - mnew);
        float p1 = __expf(s1 - mnew);
        float lt = p0 + p1;
#pragma unroll
        for (int off = 16; off > 0; off >>= 1)
            lt += __shfl_xor_sync(0xffffffffu, lt, off);
        l = l * scale + lt;
        acc0 *= scale; acc1 *= scale;
        m = mnew;

        Ps[warp][lane] = p0;
        Ps[warp][lane + 32] = p1;
        __syncwarp();
#pragma unroll 8
        for (int j = 0; j < 64; ++j) {
            float p = Ps[warp][j];
            acc0 += p * Vs[j * 65 + lane];
            acc1 += p * Vs[j * 65 + lane + 32];
        }
        __syncwarp();
    }

    int b = bh >> 4, h = bh & 15;
    float inv = 1.f / l;
    size_t o_off = ((size_t)b * T_ + qi) * C_ + h * HD_;
    g_o[o_off + lane]      = acc0 * inv;
    g_o[o_off + lane + 32] = acc1 * inv;
}

// ---------------------------------------------------------------------------
extern "C" void kernel_launch(void* const* d_in, const int* in_sizes, int n_in,
                              void* d_out, int out_size) {
    const float* x    = (const float*)d_in[0];
    const float* Wqkv = (const float*)d_in[1];
    const float* bqkv = (const float*)d_in[2];
    const float* Wout = (const float*)d_in[3];
    const float* bout = (const float*)d_in[4];

    float* y = (float*)d_out;
    float* k = y + (size_t)B_ * T_ * C_;
    float* v = k + (size_t)B_ * T_ * C_;

    static int configured = 0;
    if (!configured) {
        cudaFuncSetAttribute((const void*)qkv_gemm,
                             cudaFuncAttributeMaxDynamicSharedMemorySize, SMEM_BYTES);
        cudaFuncSetAttribute((const void*)out_gemm,
                             cudaFuncAttributeMaxDynamicSharedMemorySize, SMEM_BYTES);
        configured = 1;
    }

    qkv_gemm<<<dim3(3 * C_ / 128, M_ / 128), 256, SMEM_BYTES>>>(x, Wqkv, bqkv, k, v);
    attn_kernel<<<dim3(T_ / AT_WARPS, B_ * NH_), 512>>>(k, v);
    out_gemm<<<dim3(C_ / 128, M_ / 128), 256, SMEM_BYTES>>>(Wout, bout, y);
}

// round 8
// speedup vs baseline: 5.5841x; 4.3142x over previous
#include <cuda_runtime.h>
#include <cuda_bf16.h>
#include <math.h>
#include <stdint.h>

#define B_ 4
#define T_ 2048
#define C_ 1024
#define NH_ 16
#define HD_ 64
#define M_ (B_*T_)   // 8192

// Scratch (no allocations allowed): q in [B,NH,T,HD], attention output in [B,T,C]
__device__ float g_q[(size_t)B_*NH_*T_*HD_];
__device__ float g_o[(size_t)B_*T_*C_];

__device__ __forceinline__ uint32_t f2tf32(float f) {
    uint32_t u;
    asm("cvt.rna.tf32.f32 %0, %1;" : "=r"(u) : "f"(f));
    return u;
}

__device__ __forceinline__ void cp16(float* smem_dst, const float* gmem_src) {
    uint32_t s = (uint32_t)__cvta_generic_to_shared(smem_dst);
    asm volatile("cp.async.cg.shared.global [%0], [%1], 16;" :: "r"(s), "l"(gmem_src));
}

__device__ __forceinline__ void mma_tf32(float* cc, const uint32_t* a,
                                         uint32_t b0, uint32_t b1) {
    asm volatile(
        "mma.sync.aligned.m16n8k8.row.col.f32.tf32.tf32.f32 "
        "{%0,%1,%2,%3}, {%4,%5,%6,%7}, {%8,%9}, {%0,%1,%2,%3};"
        : "+f"(cc[0]), "+f"(cc[1]), "+f"(cc[2]), "+f"(cc[3])
        : "r"(a[0]), "r"(a[1]), "r"(a[2]), "r"(a[3]), "r"(b0), "r"(b1));
}

// ---------------------------------------------------------------------------
// Tensor-core tf32 GEMM machinery (mma.sync.m16n8k8)  — unchanged from R3
// ---------------------------------------------------------------------------
#define AS_STRIDE 36
#define BS_STRIDE 136
#define AS_STAGE (128*AS_STRIDE)
#define BS_STAGE (32*BS_STRIDE)
#define SMEM_FLOATS (2*AS_STAGE + 2*BS_STAGE)
#define SMEM_BYTES (SMEM_FLOATS*4) // 71680

__device__ __forceinline__ void gemm_mainloop(
    const float* __restrict__ A, int lda,
    const float* __restrict__ B, int ldb,
    int K, int m0, int n0, float* sm, float acc[2][8][4])
{
    float* As = sm;
    float* Bs = sm + 2 * AS_STAGE;
    const int tid = threadIdx.x;
    const int lane = tid & 31, warp = tid >> 5;
    const int r = lane >> 2, c = lane & 3;
    const int mb = (warp & 3) * 32, nb = (warp >> 2) * 64;
    const int ITERS = K / 32;

    auto issue_load = [&](int stage, int k0) {
#pragma unroll
        for (int i = 0; i < 4; ++i) {
            int idx = tid + i * 256;
            int ar = idx >> 3, ac = (idx & 7) * 4;
            cp16(&As[stage * AS_STAGE + ar * AS_STRIDE + ac],
                 A + (size_t)(m0 + ar) * lda + k0 + ac);
            int br = idx >> 5, bc = (idx & 31) * 4;
            cp16(&Bs[stage * BS_STAGE + br * BS_STRIDE + bc],
                 B + (size_t)(k0 + br) * ldb + n0 + bc);
        }
        asm volatile("cp.async.commit_group;");
    };

    issue_load(0, 0);

    for (int it = 0; it < ITERS; ++it) {
        if (it + 1 < ITERS) {
            issue_load((it + 1) & 1, (it + 1) * 32);
            asm volatile("cp.async.wait_group 1;");
        } else {
            asm volatile("cp.async.wait_group 0;");
        }
        __syncthreads();

        const float* as = As + (it & 1) * AS_STAGE;
        const float* bs = Bs + (it & 1) * BS_STAGE;
#pragma unroll
        for (int ks = 0; ks < 4; ++ks) {
            int kb = ks * 8;
            uint32_t afrag[2][4];
#pragma unroll
            for (int mt = 0; mt < 2; ++mt) {
                int row = mb + mt * 16;
                afrag[mt][0] = f2tf32(as[(row + r) * AS_STRIDE + kb + c]);
                afrag[mt][1] = f2tf32(as[(row + r + 8) * AS_STRIDE + kb + c]);
                afrag[mt][2] = f2tf32(as[(row + r) * AS_STRIDE + kb + c + 4]);
                afrag[mt][3] = f2tf32(as[(row + r + 8) * AS_STRIDE + kb + c + 4]);
            }
#pragma unroll
            for (int nt = 0; nt < 8; ++nt) {
                int col = nb + nt * 8 + r;
                uint32_t b0 = f2tf32(bs[(kb + c) * BS_STRIDE + col]);
                uint32_t b1 = f2tf32(bs[(kb + c + 4) * BS_STRIDE + col]);
#pragma unroll
                for (int mt = 0; mt < 2; ++mt)
                    mma_tf32(acc[mt][nt], afrag[mt], b0, b1);
            }
        }
        __syncthreads();
    }
}

// ---------------------------------------------------------------------------
// QKV GEMM (unchanged)
// ---------------------------------------------------------------------------
__global__ __launch_bounds__(256) void qkv_gemm(const float* __restrict__ X,
                                                const float* __restrict__ W,
                                                const float* __restrict__ bias,
                                                float* __restrict__ outK,
                                                float* __restrict__ outV) {
    extern __shared__ float sm[];
    int m0 = blockIdx.y * 128, n0 = blockIdx.x * 128;
    float acc[2][8][4];
#pragma unroll
    for (int i = 0; i < 2; ++i)
#pragma unroll
        for (int j = 0; j < 8; ++j)
#pragma unroll
            for (int p = 0; p < 4; ++p) acc[i][j][p] = 0.f;

    gemm_mainloop(X, C_, W, 3 * C_, C_, m0, n0, sm, acc);

    const int lane = threadIdx.x & 31, warp = threadIdx.x >> 5;
    const int r = lane >> 2, c = lane & 3;
    const int mb = (warp & 3) * 32, nb = (warp >> 2) * 64;

#pragma unroll
    for (int mt = 0; mt < 2; ++mt) {
#pragma unroll
        for (int nt = 0; nt < 8; ++nt) {
            int n = n0 + nb + nt * 8 + 2 * c;
            float bx = bias[n], by = bias[n + 1];
            int region = n >> 10;
            int cc = n & (C_ - 1);
            int h = cc >> 6, d = cc & 63;
            float* dstbase = (region == 0) ? g_q : (region == 1) ? outK : outV;
#pragma unroll
            for (int half = 0; half < 2; ++half) {
                int m = m0 + mb + mt * 16 + r + half * 8;
                int bb = m >> 11, t = m & (T_ - 1);
                size_t dst = ((size_t)(bb * NH_ + h) * T_ + t) * HD_ + d;
                float2 v2;
                v2.x = acc[mt][nt][half * 2 + 0] + bx;
                v2.y = acc[mt][nt][half * 2 + 1] + by;
                *(float2*)(dstbase + dst) = v2;
            }
        }
    }
}

// ---------------------------------------------------------------------------
// Output projection GEMM (unchanged)
// ---------------------------------------------------------------------------
__global__ __launch_bounds__(256) void out_gemm(const float* __restrict__ W,
                                                const float* __restrict__ bias,
                                                float* __restrict__ Y) {
    extern __shared__ float sm[];
    int m0 = blockIdx.y * 128, n0 = blockIdx.x * 128;
    float acc[2][8][4];
#pragma unroll
    for (int i = 0; i < 2; ++i)
#pragma unroll
        for (int j = 0; j < 8; ++j)
#pragma unroll
            for (int p = 0; p < 4; ++p) acc[i][j][p] = 0.f;

    gemm_mainloop(g_o, C_, W, C_, C_, m0, n0, sm, acc);

    const int lane = threadIdx.x & 31, warp = threadIdx.x >> 5;
    const int r = lane >> 2, c = lane & 3;
    const int mb = (warp & 3) * 32, nb = (warp >> 2) * 64;

#pragma unroll
    for (int mt = 0; mt < 2; ++mt) {
#pragma unroll
        for (int nt = 0; nt < 8; ++nt) {
            int n = n0 + nb + nt * 8 + 2 * c;
            float bx = bias[n], by = bias[n + 1];
#pragma unroll
            for (int half = 0; half < 2; ++half) {
                int m = m0 + mb + mt * 16 + r + half * 8;
                float2 v2;
                v2.x = acc[mt][nt][half * 2 + 0] + bx;
                v2.y = acc[mt][nt][half * 2 + 1] + by;
                *(float2*)(Y + (size_t)m * C_ + n) = v2;
            }
        }
    }
}

// ---------------------------------------------------------------------------
// Tensor-core flash attention (tf32 mma, fp32 online softmax, causal).
// BM=64 q-rows per CTA (4 warps x 16 rows), BN=64 key tile.
// K/V/P staged in smem PRE-CONVERTED to tf32 bits (cvt once per element).
// Strides: Ks/Ps 68 (frag bank = 4r+c, conflict-free), Vs 72 (8c+r, c-f).
// ---------------------------------------------------------------------------
#define KS_STRIDE 68
#define VS_STRIDE 72
#define PS_STRIDE 68
#define ATT_SMEM_FLOATS (64*KS_STRIDE + 64*VS_STRIDE + 64*PS_STRIDE)
#define ATT_SMEM_BYTES (ATT_SMEM_FLOATS*4)   // 53248

__global__ __launch_bounds__(128) void attn_tc(const float* __restrict__ gk,
                                               const float* __restrict__ gv) {
    extern __shared__ float sm[];
    uint32_t* Ks = (uint32_t*)sm;                       // [64][KS_STRIDE] tf32 bits
    uint32_t* Vs = Ks + 64 * KS_STRIDE;                 // [64][VS_STRIDE]
    uint32_t* Ps = Vs + 64 * VS_STRIDE;                 // [64][PS_STRIDE]

    const int bh = blockIdx.y;
    const int q0 = blockIdx.x * 64;
    const int tid = threadIdx.x, lane = tid & 31, warp = tid >> 5;
    const int r = lane >> 2, c = lane & 3;

    const float* qbase = g_q + (size_t)bh * T_ * HD_;
    const float* kbase = gk + (size_t)bh * T_ * HD_;
    const float* vbase = gv + (size_t)bh * T_ * HD_;

    // Q fragments, scale 1/8 folded in, tf32-rounded once.
    const int qrow0 = q0 + warp * 16;
    uint32_t qf[8][4];
#pragma unroll
    for (int kg = 0; kg < 8; ++kg) {
        qf[kg][0] = f2tf32(qbase[(size_t)(qrow0 + r)     * HD_ + kg * 8 + c]     * 0.125f);
        qf[kg][1] = f2tf32(qbase[(size_t)(qrow0 + r + 8) * HD_ + kg * 8 + c]     * 0.125f);
        qf[kg][2] = f2tf32(qbase[(size_t)(qrow0 + r)     * HD_ + kg * 8 + c + 4] * 0.125f);
        qf[kg][3] = f2tf32(qbase[(size_t)(qrow0 + r + 8) * HD_ + kg * 8 + c + 4] * 0.125f);
    }

    float acc_o[8][4];
#pragma unroll
    for (int i = 0; i < 8; ++i)
#pragma unroll
        for (int j = 0; j < 4; ++j) acc_o[i][j] = 0.f;
    float m0v = -INFINITY, m1v = -INFINITY, l0 = 0.f, l1 = 0.f;

    const int ntiles = q0 / 64 + 1;
    for (int t = 0; t < ntiles; ++t) {
        const int j0 = t * 64;
        __syncthreads();
        // cooperative load + cvt of K,V tile (64x64 each, float4 granularity)
        for (int i = tid; i < 64 * 16; i += 128) {
            int row = i >> 4, c4 = (i & 15) * 4;
            float4 kk = *(const float4*)(kbase + (size_t)(j0 + row) * HD_ + c4);
            float4 vv = *(const float4*)(vbase + (size_t)(j0 + row) * HD_ + c4);
            uint4 ku = make_uint4(f2tf32(kk.x), f2tf32(kk.y), f2tf32(kk.z), f2tf32(kk.w));
            uint4 vu = make_uint4(f2tf32(vv.x), f2tf32(vv.y), f2tf32(vv.z), f2tf32(vv.w));
            *(uint4*)&Ks[row * KS_STRIDE + c4] = ku;
            *(uint4*)&Vs[row * VS_STRIDE + c4] = vu;
        }
        __syncthreads();

        // S = (Q/8) K^T  [16 x 64 per warp]
        float accs[8][4];
#pragma unroll
        for (int i = 0; i < 8; ++i)
#pragma unroll
            for (int j = 0; j < 4; ++j) accs[i][j] = 0.f;
#pragma unroll
        for (int kg = 0; kg < 8; ++kg) {
#pragma unroll
            for (int nt = 0; nt < 8; ++nt) {
                uint32_t b0 = Ks[(nt * 8 + r) * KS_STRIDE + kg * 8 + c];
                uint32_t b1 = Ks[(nt * 8 + r) * KS_STRIDE + kg * 8 + c + 4];
                mma_tf32(accs[nt], qf[kg], b0, b1);
            }
        }

        // causal mask (edge tile only; per-warp uniform branch)
        if (j0 + 63 > qrow0) {
#pragma unroll
            for (int nt = 0; nt < 8; ++nt) {
#pragma unroll
                for (int e = 0; e < 4; ++e) {
                    int j = j0 + nt * 8 + 2 * c + (e & 1);
                    int q = qrow0 + r + 8 * (e >> 1);
                    if (j > q) accs[nt][e] = -INFINITY;
                }
            }
        }

        // online softmax (rows r and r+8)
        float mt0 = -INFINITY, mt1 = -INFINITY;
#pragma unroll
        for (int nt = 0; nt < 8; ++nt) {
            mt0 = fmaxf(mt0, fmaxf(accs[nt][0], accs[nt][1]));
            mt1 = fmaxf(mt1, fmaxf(accs[nt][2], accs[nt][3]));
        }
        mt0 = fmaxf(mt0, __shfl_xor_sync(0xffffffffu, mt0, 1));
        mt0 = fmaxf(mt0, __shfl_xor_sync(0xffffffffu, mt0, 2));
        mt1 = fmaxf(mt1, __shfl_xor_sync(0xffffffffu, mt1, 1));
        mt1 = fmaxf(mt1, __shfl_xor_sync(0xffffffffu, mt1, 2));
        float mn0 = fmaxf(m0v, mt0), mn1 = fmaxf(m1v, mt1);
        float sc0 = __expf(m0v - mn0), sc1 = __expf(m1v - mn1);

        float ps0 = 0.f, ps1 = 0.f;
#pragma unroll
        for (int nt = 0; nt < 8; ++nt) {
            float p0 = __expf(accs[nt][0] - mn0);
            float p1 = __expf(accs[nt][1] - mn0);
            float p2 = __expf(accs[nt][2] - mn1);
            float p3 = __expf(accs[nt][3] - mn1);
            ps0 += p0 + p1; ps1 += p2 + p3;
            int col = nt * 8 + 2 * c;
            Ps[(warp * 16 + r)     * PS_STRIDE + col]     = f2tf32(p0);
            Ps[(warp * 16 + r)     * PS_STRIDE + col + 1] = f2tf32(p1);
            Ps[(warp * 16 + r + 8) * PS_STRIDE + col]     = f2tf32(p2);
            Ps[(warp * 16 + r + 8) * PS_STRIDE + col + 1] = f2tf32(p3);
        }
        ps0 += __shfl_xor_sync(0xffffffffu, ps0, 1);
        ps0 += __shfl_xor_sync(0xffffffffu, ps0, 2);
        ps1 += __shfl_xor_sync(0xffffffffu, ps1, 1);
        ps1 += __shfl_xor_sync(0xffffffffu, ps1, 2);
        l0 = l0 * sc0 + ps0;
        l1 = l1 * sc1 + ps1;
        m0v = mn0; m1v = mn1;
#pragma unroll
        for (int nt = 0; nt < 8; ++nt) {
            acc_o[nt][0] *= sc0; acc_o[nt][1] *= sc0;
            acc_o[nt][2] *= sc1; acc_o[nt][3] *= sc1;
        }
        __syncwarp();

        // O += P V   [16 x 64 per warp, k-dim = 64 keys]
#pragma unroll
        for (int kg = 0; kg < 8; ++kg) {
            uint32_t a[4];
            a[0] = Ps[(warp * 16 + r)     * PS_STRIDE + kg * 8 + c];
            a[1] = Ps[(warp * 16 + r + 8) * PS_STRIDE + kg * 8 + c];
            a[2] = Ps[(warp * 16 + r)     * PS_STRIDE + kg * 8 + c + 4];
            a[3] = Ps[(warp * 16 + r + 8) * PS_STRIDE + kg * 8 + c + 4];
#pragma unroll
            for (int nt = 0; nt < 8; ++nt) {
                uint32_t b0 = Vs[(kg * 8 + c)     * VS_STRIDE + nt * 8 + r];
                uint32_t b1 = Vs[(kg * 8 + c + 4) * VS_STRIDE + nt * 8 + r];
                mma_tf32(acc_o[nt], a, b0, b1);
            }
        }
        __syncwarp();
    }

    // write O[b, t, h*64 + d] = acc / l
    const int b = bh >> 4, h = bh & 15;
    float inv0 = 1.f / l0, inv1 = 1.f / l1;
    size_t row0 = ((size_t)b * T_ + qrow0 + r)     * C_ + h * HD_;
    size_t row1 = ((size_t)b * T_ + qrow0 + r + 8) * C_ + h * HD_;
#pragma unroll
    for (int nt = 0; nt < 8; ++nt) {
        int col = nt * 8 + 2 * c;
        float2 v0 = make_float2(acc_o[nt][0] * inv0, acc_o[nt][1] * inv0);
        float2 v1 = make_float2(acc_o[nt][2] * inv1, acc_o[nt][3] * inv1);
        *(float2*)(g_o + row0 + col) = v0;
        *(float2*)(g_o + row1 + col) = v1;
    }
}

// ---------------------------------------------------------------------------
extern "C" void kernel_launch(void* const* d_in, const int* in_sizes, int n_in,
                              void* d_out, int out_size) {
    const float* x    = (const float*)d_in[0];
    const float* Wqkv = (const float*)d_in[1];
    const float* bqkv = (const float*)d_in[2];
    const float* Wout = (const float*)d_in[3];
    const float* bout = (const float*)d_in[4];

    float* y = (float*)d_out;
    float* k = y + (size_t)B_ * T_ * C_;
    float* v = k + (size_t)B_ * T_ * C_;

    static int configured = 0;
    if (!configured) {
        cudaFuncSetAttribute((const void*)qkv_gemm,
                             cudaFuncAttributeMaxDynamicSharedMemorySize, SMEM_BYTES);
        cudaFuncSetAttribute((const void*)out_gemm,
                             cudaFuncAttributeMaxDynamicSharedMemorySize, SMEM_BYTES);
        cudaFuncSetAttribute((const void*)attn_tc,
                             cudaFuncAttributeMaxDynamicSharedMemorySize, ATT_SMEM_BYTES);
        configured = 1;
    }

    qkv_gemm<<<dim3(3 * C_ / 128, M_ / 128), 256, SMEM_BYTES>>>(x, Wqkv, bqkv, k, v);
    attn_tc<<<dim3(T_ / 64, B_ * NH_), 128, ATT_SMEM_BYTES>>>(k, v);
    out_gemm<<<dim3(C_ / 128, M_ / 128), 256, SMEM_BYTES>>>(Wout, bout, y);
}

// round 12
// speedup vs baseline: 5.9664x; 1.0685x over previous
#include <cuda_runtime.h>
#include <cuda_bf16.h>
#include <math.h>
#include <stdint.h>

#define B_ 4
#define T_ 2048
#define C_ 1024
#define NH_ 16
#define HD_ 64
#define M_ (B_*T_)   // 8192

// Scratch (no allocations allowed).
__device__ float    g_q[(size_t)B_*NH_*T_*HD_];        // Q in [B,NH,T,HD] (float)
__device__ uint32_t g_op[(size_t)M_*C_];               // attn out, tf32 bits, A-frag layout
__device__ uint32_t g_xp[(size_t)M_*C_];               // x, tf32 bits, A-frag layout
__device__ uint32_t g_wqkvp[(size_t)C_*3*C_];          // W_qkv, tf32 bits, B-frag layout
__device__ uint32_t g_woutp[(size_t)C_*C_];            // W_out, tf32 bits, B-frag layout

__device__ __forceinline__ uint32_t f2tf32(float f) {
    uint32_t u;
    asm("cvt.rna.tf32.f32 %0, %1;" : "=r"(u) : "f"(f));
    return u;
}

__device__ __forceinline__ void cp16(void* smem_dst, const void* gmem_src) {
    uint32_t s = (uint32_t)__cvta_generic_to_shared(smem_dst);
    asm volatile("cp.async.cg.shared.global [%0], [%1], 16;" :: "r"(s), "l"(gmem_src));
}

__device__ __forceinline__ void mma_tf32(float* cc, const uint32_t* a,
                                         uint32_t b0, uint32_t b1) {
    asm volatile(
        "mma.sync.aligned.m16n8k8.row.col.f32.tf32.tf32.f32 "
        "{%0,%1,%2,%3}, {%4,%5,%6,%7}, {%8,%9}, {%0,%1,%2,%3};"
        : "+f"(cc[0]), "+f"(cc[1]), "+f"(cc[2]), "+f"(cc[3])
        : "r"(a[0]), "r"(a[1]), "r"(a[2]), "r"(a[3]), "r"(b0), "r"(b1));
}

// ---------------------------------------------------------------------------
// Pre-pass: convert fp32 -> tf32 bits, permute into mma fragment order.
// A-layout (row-major operand, m16k8 tiles):
//   dst[((m>>4)*Ktiles + (k>>3))*128 + ((m&7)*4 + (k&3))*4 + ((k>>2)&1)*2 + ((m>>3)&1)]
// B-layout (col-major operand of m16n8k8, k8n8 tiles):
//   dst[((n>>3)*Ktiles + (k>>3))*64 + ((n&7)*4 + (k&3))*2 + ((k>>2)&1)]
// ---------------------------------------------------------------------------
__global__ void permA(const float* __restrict__ src, uint32_t* __restrict__ dst,
                      int Mrows, int Kdim) {
    int Ktiles = Kdim >> 3;
    size_t total4 = (size_t)Mrows * Kdim / 4;
    for (size_t i4 = (size_t)blockIdx.x * blockDim.x + threadIdx.x; i4 < total4;
         i4 += (size_t)gridDim.x * blockDim.x) {
        size_t idx = i4 * 4;
        int m = (int)(idx / Kdim), k = (int)(idx % Kdim);   // k % 4 == 0
        float4 v = *(const float4*)(src + idx);
        size_t base = ((size_t)(m >> 4) * Ktiles + (k >> 3)) * 128;
        int e = ((k >> 2) & 1) * 2 + ((m >> 3) & 1);
        int l0 = (m & 7) * 4;                               // + (k&3)=0..3
        dst[base + (l0 + 0) * 4 + e] = f2tf32(v.x);
        dst[base + (l0 + 1) * 4 + e] = f2tf32(v.y);
        dst[base + (l0 + 2) * 4 + e] = f2tf32(v.z);
        dst[base + (l0 + 3) * 4 + e] = f2tf32(v.w);
    }
}

__global__ void permB(const float* __restrict__ src, uint32_t* __restrict__ dst,
                      int Kdim, int N) {
    int Ktiles = Kdim >> 3;
    size_t total4 = (size_t)Kdim * N / 4;
    for (size_t i4 = (size_t)blockIdx.x * blockDim.x + threadIdx.x; i4 < total4;
         i4 += (size_t)gridDim.x * blockDim.x) {
        size_t idx = i4 * 4;
        int k = (int)(idx / N), n = (int)(idx % N);          // n % 4 == 0
        float4 v = *(const float4*)(src + idx);
        size_t base = ((size_t)(n >> 3) * Ktiles + (k >> 3)) * 64;
        int e = (k >> 2) & 1;
        int kc = k & 3;
        dst[base + (((n & 7) + 0) * 4 + kc) * 2 + e] = f2tf32(v.x);
        dst[base + (((n & 7) + 1) * 4 + kc) * 2 + e] = f2tf32(v.y);
        dst[base + (((n & 7) + 2) * 4 + kc) * 2 + e] = f2tf32(v.z);
        dst[base + (((n & 7) + 3) * 4 + kc) * 2 + e] = f2tf32(v.w);
    }
}

// ---------------------------------------------------------------------------
// GEMM mainloop on pre-converted, fragment-ordered operands. No cvt, wide LDS.
// Block 128x128, BK=32 (4 k-tiles), 256 threads, 8 warps of 32x64.
// Smem per stage: A 8*4*128 = 4096 u32 (16KB), B 16*4*64 = 4096 u32 (16KB).
// ---------------------------------------------------------------------------
#define GSM_U32 (4*4096)
#define SMEM_BYTES (GSM_U32*4)   // 65536

__device__ __forceinline__ void gemm_mainloop_p(
    const uint32_t* __restrict__ Ap, const uint32_t* __restrict__ Bp,
    int Ktiles, int m0, int n0, uint32_t* sm, float acc[2][8][4])
{
    uint32_t* As = sm;              // [2][4096]
    uint32_t* Bs = sm + 2 * 4096;   // [2][4096]
    const int tid = threadIdx.x, lane = tid & 31, warp = tid >> 5;
    const int mt0 = (warp & 3) * 2;     // A m-tile base (of 8 per block)
    const int ntb = (warp >> 2) * 8;    // B n-tile base (of 16 per block)
    const int ITERS = Ktiles / 4;

    auto issue_load = [&](int stage, int kt0) {
#pragma unroll
        for (int i = 0; i < 4; ++i) {
            int idx = tid + i * 256;                    // 0..1023 (16B units)
            int ach = idx >> 7, au = idx & 127;         // 8 A chunks x 128 units
            cp16(As + stage * 4096 + ach * 512 + au * 4,
                 Ap + (((size_t)((m0 >> 4) + ach) * Ktiles + kt0) * 128) + au * 4);
            int bch = idx >> 6, bu = idx & 63;          // 16 B chunks x 64 units
            cp16(Bs + stage * 4096 + bch * 256 + bu * 4,
                 Bp + (((size_t)((n0 >> 3) + bch) * Ktiles + kt0) * 64) + bu * 4);
        }
        asm volatile("cp.async.commit_group;");
    };

    issue_load(0, 0);

    for (int it = 0; it < ITERS; ++it) {
        if (it + 1 < ITERS) {
            issue_load((it + 1) & 1, (it + 1) * 4);
            asm volatile("cp.async.wait_group 1;");
        } else {
            asm volatile("cp.async.wait_group 0;");
        }
        __syncthreads();

        const uint32_t* as = As + (it & 1) * 4096;
        const uint32_t* bs = Bs + (it & 1) * 4096;
#pragma unroll
        for (int ks = 0; ks < 4; ++ks) {
            uint4 a0 = *(const uint4*)&as[((mt0 + 0) * 4 + ks) * 128 + lane * 4];
            uint4 a1 = *(const uint4*)&as[((mt0 + 1) * 4 + ks) * 128 + lane * 4];
#pragma unroll
            for (int nt = 0; nt < 8; ++nt) {
                uint2 b = *(const uint2*)&bs[((ntb + nt) * 4 + ks) * 64 + lane * 2];
                mma_tf32(acc[0][nt], (const uint32_t*)&a0, b.x, b.y);
                mma_tf32(acc[1][nt], (const uint32_t*)&a1, b.x, b.y);
            }
        }
        __syncthreads();
    }
}

// ---------------------------------------------------------------------------
// QKV GEMM: g_xp[M,C] @ g_wqkvp[C,3C] + b, scatter epilogue (q/k/v split).
// ---------------------------------------------------------------------------
__global__ __launch_bounds__(256) void qkv_gemm(const float* __restrict__ bias,
                                                float* __restrict__ outK,
                                                float* __restrict__ outV) {
    extern __shared__ uint32_t sm[];
    int m0 = blockIdx.y * 128, n0 = blockIdx.x * 128;
    float acc[2][8][4];
#pragma unroll
    for (int i = 0; i < 2; ++i)
#pragma unroll
        for (int j = 0; j < 8; ++j)
#pragma unroll
            for (int p = 0; p < 4; ++p) acc[i][j][p] = 0.f;

    gemm_mainloop_p(g_xp, g_wqkvp, C_ / 8, m0, n0, sm, acc);

    const int lane = threadIdx.x & 31, warp = threadIdx.x >> 5;
    const int r = lane >> 2, c = lane & 3;
    const int mb = (warp & 3) * 32, nb = (warp >> 2) * 64;

#pragma unroll
    for (int mt = 0; mt < 2; ++mt) {
#pragma unroll
        for (int nt = 0; nt < 8; ++nt) {
            int n = n0 + nb + nt * 8 + 2 * c;
            float bx = bias[n], by = bias[n + 1];
            int region = n >> 10;
            int cc = n & (C_ - 1);
            int h = cc >> 6, d = cc & 63;
            float* dstbase = (region == 0) ? g_q : (region == 1) ? outK : outV;
#pragma unroll
            for (int half = 0; half < 2; ++half) {
                int m = m0 + mb + mt * 16 + r + half * 8;
                int bb = m >> 11, t = m & (T_ - 1);
                size_t dst = ((size_t)(bb * NH_ + h) * T_ + t) * HD_ + d;
                float2 v2;
                v2.x = acc[mt][nt][half * 2 + 0] + bx;
                v2.y = acc[mt][nt][half * 2 + 1] + by;
                *(float2*)(dstbase + dst) = v2;
            }
        }
    }
}

// ---------------------------------------------------------------------------
// Output projection: g_op[M,C] @ g_woutp[C,C] + b_out -> y
// ---------------------------------------------------------------------------
__global__ __launch_bounds__(256) void out_gemm(const float* __restrict__ bias,
                                                float* __restrict__ Y) {
    extern __shared__ uint32_t sm[];
    int m0 = blockIdx.y * 128, n0 = blockIdx.x * 128;
    float acc[2][8][4];
#pragma unroll
    for (int i = 0; i < 2; ++i)
#pragma unroll
        for (int j = 0; j < 8; ++j)
#pragma unroll
            for (int p = 0; p < 4; ++p) acc[i][j][p] = 0.f;

    gemm_mainloop_p(g_op, g_woutp, C_ / 8, m0, n0, sm, acc);

    const int lane = threadIdx.x & 31, warp = threadIdx.x >> 5;
    const int r = lane >> 2, c = lane & 3;
    const int mb = (warp & 3) * 32, nb = (warp >> 2) * 64;

#pragma unroll
    for (int mt = 0; mt < 2; ++mt) {
#pragma unroll
        for (int nt = 0; nt < 8; ++nt) {
            int n = n0 + nb + nt * 8 + 2 * c;
            float bx = bias[n], by = bias[n + 1];
#pragma unroll
            for (int half = 0; half < 2; ++half) {
                int m = m0 + mb + mt * 16 + r + half * 8;
                float2 v2;
                v2.x = acc[mt][nt][half * 2 + 0] + bx;
                v2.y = acc[mt][nt][half * 2 + 1] + by;
                *(float2*)(Y + (size_t)m * C_ + n) = v2;
            }
        }
    }
}

// ---------------------------------------------------------------------------
// Tensor-core flash attention (unchanged compute; epilogue now writes g_op
// in A-fragment tf32-bit layout for out_gemm).
// ---------------------------------------------------------------------------
#define KS_STRIDE 68
#define VS_STRIDE 72
#define PS_STRIDE 68
#define ATT_SMEM_FLOATS (64*KS_STRIDE + 64*VS_STRIDE + 64*PS_STRIDE)
#define ATT_SMEM_BYTES (ATT_SMEM_FLOATS*4)   // 53248

__global__ __launch_bounds__(128) void attn_tc(const float* __restrict__ gk,
                                               const float* __restrict__ gv) {
    extern __shared__ uint32_t smu[];
    uint32_t* Ks = smu;
    uint32_t* Vs = Ks + 64 * KS_STRIDE;
    uint32_t* Ps = Vs + 64 * VS_STRIDE;

    const int bh = blockIdx.y;
    const int q0 = blockIdx.x * 64;
    const int tid = threadIdx.x, lane = tid & 31, warp = tid >> 5;
    const int r = lane >> 2, c = lane & 3;

    const float* qbase = g_q + (size_t)bh * T_ * HD_;
    const float* kbase = gk + (size_t)bh * T_ * HD_;
    const float* vbase = gv + (size_t)bh * T_ * HD_;

    const int qrow0 = q0 + warp * 16;
    uint32_t qf[8][4];
#pragma unroll
    for (int kg = 0; kg < 8; ++kg) {
        qf[kg][0] = f2tf32(qbase[(size_t)(qrow0 + r)     * HD_ + kg * 8 + c]     * 0.125f);
        qf[kg][1] = f2tf32(qbase[(size_t)(qrow0 + r + 8) * HD_ + kg * 8 + c]     * 0.125f);
        qf[kg][2] = f2tf32(qbase[(size_t)(qrow0 + r)     * HD_ + kg * 8 + c + 4] * 0.125f);
        qf[kg][3] = f2tf32(qbase[(size_t)(qrow0 + r + 8) * HD_ + kg * 8 + c + 4] * 0.125f);
    }

    float acc_o[8][4];
#pragma unroll
    for (int i = 0; i < 8; ++i)
#pragma unroll
        for (int j = 0; j < 4; ++j) acc_o[i][j] = 0.f;
    float m0v = -INFINITY, m1v = -INFINITY, l0 = 0.f, l1 = 0.f;

    const int ntiles = q0 / 64 + 1;
    for (int t = 0; t < ntiles; ++t) {
        const int j0 = t * 64;
        __syncthreads();
        for (int i = tid; i < 64 * 16; i += 128) {
            int row = i >> 4, c4 = (i & 15) * 4;
            float4 kk = *(const float4*)(kbase + (size_t)(j0 + row) * HD_ + c4);
            float4 vv = *(const float4*)(vbase + (size_t)(j0 + row) * HD_ + c4);
            uint4 ku = make_uint4(f2tf32(kk.x), f2tf32(kk.y), f2tf32(kk.z), f2tf32(kk.w));
            uint4 vu = make_uint4(f2tf32(vv.x), f2tf32(vv.y), f2tf32(vv.z), f2tf32(vv.w));
            *(uint4*)&Ks[row * KS_STRIDE + c4] = ku;
            *(uint4*)&Vs[row * VS_STRIDE + c4] = vu;
        }
        __syncthreads();

        float accs[8][4];
#pragma unroll
        for (int i = 0; i < 8; ++i)
#pragma unroll
            for (int j = 0; j < 4; ++j) accs[i][j] = 0.f;
#pragma unroll
        for (int kg = 0; kg < 8; ++kg) {
#pragma unroll
            for (int nt = 0; nt < 8; ++nt) {
                uint32_t b0 = Ks[(nt * 8 + r) * KS_STRIDE + kg * 8 + c];
                uint32_t b1 = Ks[(nt * 8 + r) * KS_STRIDE + kg * 8 + c + 4];
                mma_tf32(accs[nt], qf[kg], b0, b1);
            }
        }

        if (j0 + 63 > qrow0) {
#pragma unroll
            for (int nt = 0; nt < 8; ++nt) {
#pragma unroll
                for (int e = 0; e < 4; ++e) {
                    int j = j0 + nt * 8 + 2 * c + (e & 1);
                    int q = qrow0 + r + 8 * (e >> 1);
                    if (j > q) accs[nt][e] = -INFINITY;
                }
            }
        }

        float mt0 = -INFINITY, mt1 = -INFINITY;
#pragma unroll
        for (int nt = 0; nt < 8; ++nt) {
            mt0 = fmaxf(mt0, fmaxf(accs[nt][0], accs[nt][1]));
            mt1 = fmaxf(mt1, fmaxf(accs[nt][2], accs[nt][3]));
        }
        mt0 = fmaxf(mt0, __shfl_xor_sync(0xffffffffu, mt0, 1));
        mt0 = fmaxf(mt0, __shfl_xor_sync(0xffffffffu, mt0, 2));
        mt1 = fmaxf(mt1, __shfl_xor_sync(0xffffffffu, mt1, 1));
        mt1 = fmaxf(mt1, __shfl_xor_sync(0xffffffffu, mt1, 2));
        float mn0 = fmaxf(m0v, mt0), mn1 = fmaxf(m1v, mt1);
        float sc0 = __expf(m0v - mn0), sc1 = __expf(m1v - mn1);

        float ps0 = 0.f, ps1 = 0.f;
#pragma unroll
        for (int nt = 0; nt < 8; ++nt) {
            float p0 = __expf(accs[nt][0] - mn0);
            float p1 = __expf(accs[nt][1] - mn0);
            float p2 = __expf(accs[nt][2] - mn1);
            float p3 = __expf(accs[nt][3] - mn1);
            ps0 += p0 + p1; ps1 += p2 + p3;
            int col = nt * 8 + 2 * c;
            Ps[(warp * 16 + r)     * PS_STRIDE + col]     = f2tf32(p0);
            Ps[(warp * 16 + r)     * PS_STRIDE + col + 1] = f2tf32(p1);
            Ps[(warp * 16 + r + 8) * PS_STRIDE + col]     = f2tf32(p2);
            Ps[(warp * 16 + r + 8) * PS_STRIDE + col + 1] = f2tf32(p3);
        }
        ps0 += __shfl_xor_sync(0xffffffffu, ps0, 1);
        ps0 += __shfl_xor_sync(0xffffffffu, ps0, 2);
        ps1 += __shfl_xor_sync(0xffffffffu, ps1, 1);
        ps1 += __shfl_xor_sync(0xffffffffu, ps1, 2);
        l0 = l0 * sc0 + ps0;
        l1 = l1 * sc1 + ps1;
        m0v = mn0; m1v = mn1;
#pragma unroll
        for (int nt = 0; nt < 8; ++nt) {
            acc_o[nt][0] *= sc0; acc_o[nt][1] *= sc0;
            acc_o[nt][2] *= sc1; acc_o[nt][3] *= sc1;
        }
        __syncwarp();

#pragma unroll
        for (int kg = 0; kg < 8; ++kg) {
            uint32_t a[4];
            a[0] = Ps[(warp * 16 + r)     * PS_STRIDE + kg * 8 + c];
            a[1] = Ps[(warp * 16 + r + 8) * PS_STRIDE + kg * 8 + c];
            a[2] = Ps[(warp * 16 + r)     * PS_STRIDE + kg * 8 + c + 4];
            a[3] = Ps[(warp * 16 + r + 8) * PS_STRIDE + kg * 8 + c + 4];
#pragma unroll
            for (int nt = 0; nt < 8; ++nt) {
                uint32_t b0 = Vs[(kg * 8 + c)     * VS_STRIDE + nt * 8 + r];
                uint32_t b1 = Vs[(kg * 8 + c + 4) * VS_STRIDE + nt * 8 + r];
                mma_tf32(acc_o[nt], a, b0, b1);
            }
        }
        __syncwarp();
    }

    // Epilogue: write g_op in A-fragment tf32-bit layout.
    // m = b*T + qrow (16-aligned tiles match warp row groups); k = h*64 + col.
    const int b = bh >> 4, h = bh & 15;
    float inv0 = 1.f / l0, inv1 = 1.f / l1;
    const int mtile = b * (T_ / 16) + (qrow0 >> 4);       // global m-tile index
    const int Ktiles = C_ / 8;                            // 128
#pragma unroll
    for (int nt = 0; nt < 8; ++nt) {
        size_t base = ((size_t)mtile * Ktiles + (h * 8 + nt)) * 128;
        int kc0 = 2 * c;                                  // col within 8-tile
        int kc1 = 2 * c + 1;
        int off00 = (r * 4 + (kc0 & 3)) * 4 + ((kc0 >> 2) & 1) * 2;   // (r, kc0)
        int off01 = (r * 4 + (kc1 & 3)) * 4 + ((kc1 >> 2) & 1) * 2;   // (r, kc1)
        g_op[base + off00]     = f2tf32(acc_o[nt][0] * inv0);
        g_op[base + off01]     = f2tf32(acc_o[nt][1] * inv0);
        g_op[base + off00 + 1] = f2tf32(acc_o[nt][2] * inv1);         // (r+8, kc0)
        g_op[base + off01 + 1] = f2tf32(acc_o[nt][3] * inv1);         // (r+8, kc1)
    }
}

// ---------------------------------------------------------------------------
extern "C" void kernel_launch(void* const* d_in, const int* in_sizes, int n_in,
                              void* d_out, int out_size) {
    const float* x    = (const float*)d_in[0];
    const float* Wqkv = (const float*)d_in[1];
    const float* bqkv = (const float*)d_in[2];
    const float* Wout = (const float*)d_in[3];
    const float* bout = (const float*)d_in[4];

    float* y = (float*)d_out;
    float* k = y + (size_t)B_ * T_ * C_;
    float* v = k + (size_t)B_ * T_ * C_;

    static int configured = 0;
    if (!configured) {
        cudaFuncSetAttribute((const void*)qkv_gemm,
                             cudaFuncAttributeMaxDynamicSharedMemorySize, SMEM_BYTES);
        cudaFuncSetAttribute((const void*)out_gemm,
                             cudaFuncAttributeMaxDynamicSharedMemorySize, SMEM_BYTES);
        cudaFuncSetAttribute((const void*)attn_tc,
                             cudaFuncAttributeMaxDynamicSharedMemorySize, ATT_SMEM_BYTES);
        configured = 1;
    }

    uint32_t* xp; uint32_t* wqkvp; uint32_t* woutp;
    cudaGetSymbolAddress((void**)&xp, g_xp);
    cudaGetSymbolAddress((void**)&wqkvp, g_wqkvp);
    cudaGetSymbolAddress((void**)&woutp, g_woutp);

    permA<<<1024, 256>>>(x, xp, M_, C_);
    permB<<<1024, 256>>>(Wqkv, wqkvp, C_, 3 * C_);
    permB<<<512, 256>>>(Wout, woutp, C_, C_);

    qkv_gemm<<<dim3(3 * C_ / 128, M_ / 128), 256, SMEM_BYTES>>>(bqkv, k, v);
    attn_tc<<<dim3(T_ / 64, B_ * NH_), 128, ATT_SMEM_BYTES>>>(k, v);
    out_gemm<<<dim3(C_ / 128, M_ / 128), 256, SMEM_BYTES>>>(bout, y);
}